// round 14
// baseline (speedup 1.0000x reference)
#include <cuda_runtime.h>
#include <cuda_fp16.h>
#include <math.h>
#include <stdint.h>

#define T_STEPS 16
#define BATCH   32
#define NN      256
#define DD      128
#define HEADS   16
#define KGL     (HEADS*DD)
#define GSTEPS  5
#define NCLS    2
#define SKIPW   0.3f
#define EPSV    1e-8f

// ---------------- scratch (device globals; no allocation allowed) ------------
__device__ __half g_S [(long)T_STEPS*BATCH*NN*NN];   // RAW relu(V V^T) fp16
__device__ float g_A0 [(long)BATCH*NN*NN];           // A_final
__device__ float g_h0 [(long)BATCH*NN*DD];
__device__ float g_h1 [(long)BATCH*NN*DD];
__device__ float g_hT0[(long)BATCH*NN*DD];
__device__ float g_hT1[(long)BATCH*NN*DD];
__device__ float g_xT [(long)BATCH*NN*DD];
__device__ float g_ri [(long)T_STEPS*BATCH*NN*HEADS];
__device__ float g_rsA[(long)T_STEPS*BATCH*NN];      // rowsums (n<128) + Q01 colsums (n>=128)
__device__ float g_rsB[(long)T_STEPS*BATCH*NN];      // Q11 rowsums (n>=128)
__device__ float g_inv[(long)T_STEPS*BATCH*NN];      // wt/(rowsum+eps)
__device__ __half g_Brz_h[2*DD*2*DD];
__device__ __half g_Bh_h [DD*2*DD];
__device__ float  g_brz2[2*DD];
__device__ float  g_bh2 [DD];

// ---------------- fp16 helpers -------------------------------------------------
__device__ __forceinline__ unsigned pk2(float a, float b) {
    __half2 h = __floats2half2_rn(a, b);
    return *(unsigned*)&h;
}
__device__ __forceinline__ uint2 pk4(float4 v) {
    return make_uint2(pk2(v.x, v.y), pk2(v.z, v.w));
}
__device__ __forceinline__ unsigned hmul2u(unsigned a, unsigned b) {
    __half2 r = __hmul2(*(__half2*)&a, *(__half2*)&b);
    return *(unsigned*)&r;
}
__device__ __forceinline__ void mma_f16(float c[4], const unsigned a[4], const unsigned b[2]) {
    asm volatile(
        "mma.sync.aligned.m16n8k16.row.col.f32.f16.f16.f32 "
        "{%0,%1,%2,%3}, {%4,%5,%6,%7}, {%8,%9}, {%0,%1,%2,%3};\n"
        : "+f"(c[0]), "+f"(c[1]), "+f"(c[2]), "+f"(c[3])
        : "r"(a[0]), "r"(a[1]), "r"(a[2]), "r"(a[3]), "r"(b[0]), "r"(b[1]));
}

// ---------------- rinv: 0.25/(||x*w_h|| + eps) ---------------------------------
__global__ __launch_bounds__(128) void rinv_kernel(
    const float* __restrict__ x, const float* __restrict__ Wgl, float* __restrict__ rinv)
{
    long node = blockIdx.x;
    int tid = threadIdx.x, lane = tid & 31, w = tid >> 5;
    __shared__ float xs[DD];
    xs[tid] = x[node * DD + tid];
    __syncthreads();
    float4 xv = *(const float4*)&xs[lane * 4];
    #pragma unroll
    for (int hh = 0; hh < 4; hh++) {
        int h = w * 4 + hh;
        float4 wv = *(const float4*)&Wgl[h * DD + lane * 4];
        float a = xv.x * wv.x, b = xv.y * wv.y, c = xv.z * wv.z, d = xv.w * wv.w;
        float ss = a*a + b*b + c*c + d*d;
        #pragma unroll
        for (int o = 16; o; o >>= 1) ss += __shfl_xor_sync(0xffffffffu, ss, o);
        if (lane == 0) rinv[node * HEADS + h] = 0.25f / (sqrtf(ss) + EPSV);
    }
}

// ============ merged attention: upper (rows 0-127 x all cols) + Q11 ============
// Phase U: Q00+Q01 with raw store, rowsums, Q01 colsums, mirror Q01^T.
// Phase L: Q11 (rows/cols 128-255), reusing staged x/rinv/Wgl and stage buffers.
#define AT_ST0   0
#define AT_ST1   5120
#define AT_SX    10240      // 256 x 65 uints
#define AT_SR    26880      // 4096 floats
#define AT_SW    30976      // 2048 floats
#define AT_UINTS 33024
#define ATTA_BYTES (AT_UINTS * 4)

__global__ __launch_bounds__(256, 1) void att_kernel(
    const float* __restrict__ x, const float* __restrict__ Wgl,
    const float* __restrict__ rinv, __half* __restrict__ S,
    float* __restrict__ rsA, float* __restrict__ rsB)
{
    extern __shared__ __align__(16) unsigned smA[];
    unsigned* sX = smA + AT_SX;
    float* sR = (float*)(smA + AT_SR);
    float* sW = (float*)(smA + AT_SW);

    const int tid = threadIdx.x;
    const int lane = tid & 31, wid = tid >> 5;
    const int g = lane >> 2, t4 = lane & 3;
    const int bz = blockIdx.x;

    const float* xb = x + (long)bz * NN * DD;
    const float* rb = rinv + (long)bz * NN * HEADS;
    __half* Sb = S + (long)bz * NN * NN;

    const int myN = tid >> 3;
    const int c4  = tid & 7;

    // ---- stage x (fp16 pairs), rinv, Wgl for ALL 256 nodes ----
    #pragma unroll
    for (int it = 0; it < 32; it++) {
        int e = tid + it * 256, n = e >> 5, c = e & 31;
        float4 v = *(const float4*)&xb[(long)n * DD + c * 4];
        sX[n * 65 + c * 2]     = pk2(v.x, v.y);
        sX[n * 65 + c * 2 + 1] = pk2(v.z, v.w);
    }
    #pragma unroll
    for (int it = 0; it < 4; it++)
        ((float4*)sR)[tid + it * 256] = ((const float4*)rb)[tid + it * 256];
    #pragma unroll
    for (int it = 0; it < 2; it++)
        ((float4*)sW)[tid + it * 256] = ((const float4*)Wgl)[tid + it * 256];
    __syncthreads();

    unsigned* B0 = smA + AT_ST0;
    unsigned* B1 = smA + AT_ST1;

    // ================= Phase U: rows 0-127 x cols 0-255 =================
    {
        const int wr = (wid >> 2) * 64;            // {0,64}
        const int wc = (wid & 3) * 64;             // {0,64,128,192}
        float acc[4][8][4] = {};

        auto synth = [&](unsigned* buf, int kb) {
            int h = kb >> 7;
            int dof = (kb & 127) + c4 * 4;
            float4 ws = *(const float4*)&sW[kb + c4 * 4];
            #pragma unroll
            for (int it = 0; it < 8; it++) {
                int n = myN + it * 32;
                float rn = sR[n * 16 + h];
                int base = n * 65 + (dof >> 1);
                unsigned x0 = sX[base], x1 = sX[base + 1];
                float2 a = __half22float2(*(__half2*)&x0);
                float2 b = __half22float2(*(__half2*)&x1);
                buf[n * 20 + c4 * 2]     = pk2(a.x * ws.x * rn, a.y * ws.y * rn);
                buf[n * 20 + c4 * 2 + 1] = pk2(b.x * ws.z * rn, b.y * ws.w * rn);
            }
        };

        synth(B0, 0);
        __syncthreads();

        unsigned* cur = B0; unsigned* nxt = B1;
        for (int kbi = 0; kbi < KGL / 32; kbi++) {
            #pragma unroll
            for (int k8 = 0; k8 < 2; k8++) {
                unsigned af[4][4], bf[8][2];
                #pragma unroll
                for (int i = 0; i < 4; i++) {
                    int r = wr + i * 16 + g;
                    af[i][0] = cur[r * 20 + k8 * 8 + t4];
                    af[i][1] = cur[(r + 8) * 20 + k8 * 8 + t4];
                    af[i][2] = cur[r * 20 + k8 * 8 + t4 + 4];
                    af[i][3] = cur[(r + 8) * 20 + k8 * 8 + t4 + 4];
                }
                #pragma unroll
                for (int j = 0; j < 8; j++) {
                    int n = wc + j * 8 + g;
                    bf[j][0] = cur[n * 20 + k8 * 8 + t4];
                    bf[j][1] = cur[n * 20 + k8 * 8 + t4 + 4];
                }
                #pragma unroll
                for (int i = 0; i < 4; i++)
                    #pragma unroll
                    for (int j = 0; j < 8; j++)
                        mma_f16(acc[i][j], af[i], bf[j]);
            }
            if (kbi + 1 < KGL / 32) synth(nxt, (kbi + 1) * 32);
            __syncthreads();
            unsigned* tmp = cur; cur = nxt; nxt = tmp;
        }

        // ---- epilogue U: relu; raw store; rowsums; Q01 colsums; mirror ----
        float* rsm = (float*)smA;                    // [128][5]
        float* csm = (float*)(smA + 640);            // [128][2]
        unsigned* Tm = smA + 1024;                   // [128][66] uints
        __half* Th = (__half*)Tm;                    // half stride 132

        #pragma unroll
        for (int i = 0; i < 4; i++)
            #pragma unroll
            for (int j = 0; j < 8; j++)
                #pragma unroll
                for (int v = 0; v < 4; v++) acc[i][j][v] = fmaxf(acc[i][j][v], 0.0f);

        #pragma unroll
        for (int i = 0; i < 4; i++) {
            float s0 = 0.0f, s1 = 0.0f;
            #pragma unroll
            for (int j = 0; j < 8; j++) {
                s0 += acc[i][j][0] + acc[i][j][1];
                s1 += acc[i][j][2] + acc[i][j][3];
            }
            s0 += __shfl_xor_sync(0xffffffffu, s0, 1);
            s0 += __shfl_xor_sync(0xffffffffu, s0, 2);
            s1 += __shfl_xor_sync(0xffffffffu, s1, 1);
            s1 += __shfl_xor_sync(0xffffffffu, s1, 2);
            if (t4 == 0) {
                rsm[(wr + i * 16 + g) * 5 + (wid & 3)] = s0;
                rsm[(wr + i * 16 + g + 8) * 5 + (wid & 3)] = s1;
            }
        }
        if ((wid & 3) >= 2) {
            #pragma unroll
            for (int j = 0; j < 8; j++) {
                float c0s = 0.0f, c1s = 0.0f;
                #pragma unroll
                for (int i = 0; i < 4; i++) {
                    c0s += acc[i][j][0] + acc[i][j][2];
                    c1s += acc[i][j][1] + acc[i][j][3];
                }
                c0s += __shfl_xor_sync(0xffffffffu, c0s, 4);
                c0s += __shfl_xor_sync(0xffffffffu, c0s, 8);
                c0s += __shfl_xor_sync(0xffffffffu, c0s, 16);
                c1s += __shfl_xor_sync(0xffffffffu, c1s, 4);
                c1s += __shfl_xor_sync(0xffffffffu, c1s, 8);
                c1s += __shfl_xor_sync(0xffffffffu, c1s, 16);
                if (g == 0) {
                    int c = (wc - 128) + j * 8 + t4 * 2;
                    csm[c * 2 + (wid >> 2)]       = c0s;
                    csm[(c + 1) * 2 + (wid >> 2)] = c1s;
                }
            }
            #pragma unroll
            for (int i = 0; i < 4; i++) {
                int r0 = wr + i * 16 + g, r1 = r0 + 8;
                #pragma unroll
                for (int j = 0; j < 8; j++) {
                    int c = (wc - 128) + j * 8 + t4 * 2;
                    Th[c * 132 + r0]       = __float2half(acc[i][j][0]);
                    Th[(c + 1) * 132 + r0] = __float2half(acc[i][j][1]);
                    Th[c * 132 + r1]       = __float2half(acc[i][j][2]);
                    Th[(c + 1) * 132 + r1] = __float2half(acc[i][j][3]);
                }
            }
        }
        #pragma unroll
        for (int i = 0; i < 4; i++) {
            int r0 = wr + i * 16 + g, r1 = r0 + 8;
            #pragma unroll
            for (int j = 0; j < 8; j++) {
                int c0 = wc + j * 8 + t4 * 2;
                *(unsigned*)&Sb[(long)r0 * NN + c0] = pk2(acc[i][j][0], acc[i][j][1]);
                *(unsigned*)&Sb[(long)r1 * NN + c0] = pk2(acc[i][j][2], acc[i][j][3]);
            }
        }
        __syncthreads();
        if (tid < 128) {
            rsA[(long)bz * NN + tid] =
                rsm[tid*5] + rsm[tid*5+1] + rsm[tid*5+2] + rsm[tid*5+3];
        } else {
            int c = tid - 128;
            rsA[(long)bz * NN + 128 + c] = csm[c*2] + csm[c*2+1];
        }
        #pragma unroll
        for (int it = 0; it < 32; it++) {
            int e = tid + it * 256;
            int rr = e >> 6, cc = e & 63;
            ((unsigned*)(Sb + (long)(128 + rr) * NN))[cc] = Tm[rr * 66 + cc];
        }
    }
    __syncthreads();   // phase U epilogue (incl. Tm reads) done before reuse

    // ================= Phase L: Q11 (rows/cols 128-255) =================
    {
        const int wr = (wid >> 2) * 64;            // {0,64}
        const int wc = (wid & 3) * 32;             // {0,32,64,96}
        const int myNL = tid >> 3;                 // 0..31
        float acc[4][4][4] = {};

        auto synthL = [&](unsigned* buf, int kb) {
            int h = kb >> 7;
            int dof = (kb & 127) + c4 * 4;
            float4 ws = *(const float4*)&sW[kb + c4 * 4];
            #pragma unroll
            for (int it = 0; it < 4; it++) {
                int n = myNL + it * 32;            // local 0..127
                int gn = 128 + n;
                float rn = sR[gn * 16 + h];
                int base = gn * 65 + (dof >> 1);
                unsigned x0 = sX[base], x1 = sX[base + 1];
                float2 a = __half22float2(*(__half2*)&x0);
                float2 b = __half22float2(*(__half2*)&x1);
                buf[n * 20 + c4 * 2]     = pk2(a.x * ws.x * rn, a.y * ws.y * rn);
                buf[n * 20 + c4 * 2 + 1] = pk2(b.x * ws.z * rn, b.y * ws.w * rn);
            }
        };

        synthL(B0, 0);
        __syncthreads();

        unsigned* cur = B0; unsigned* nxt = B1;
        for (int kbi = 0; kbi < KGL / 32; kbi++) {
            #pragma unroll
            for (int k8 = 0; k8 < 2; k8++) {
                unsigned af[4][4], bf[4][2];
                #pragma unroll
                for (int i = 0; i < 4; i++) {
                    int r = wr + i * 16 + g;
                    af[i][0] = cur[r * 20 + k8 * 8 + t4];
                    af[i][1] = cur[(r + 8) * 20 + k8 * 8 + t4];
                    af[i][2] = cur[r * 20 + k8 * 8 + t4 + 4];
                    af[i][3] = cur[(r + 8) * 20 + k8 * 8 + t4 + 4];
                }
                #pragma unroll
                for (int j = 0; j < 4; j++) {
                    int n = wc + j * 8 + g;
                    bf[j][0] = cur[n * 20 + k8 * 8 + t4];
                    bf[j][1] = cur[n * 20 + k8 * 8 + t4 + 4];
                }
                #pragma unroll
                for (int i = 0; i < 4; i++)
                    #pragma unroll
                    for (int j = 0; j < 4; j++)
                        mma_f16(acc[i][j], af[i], bf[j]);
            }
            if (kbi + 1 < KGL / 32) synthL(nxt, (kbi + 1) * 32);
            __syncthreads();
            unsigned* tmp = cur; cur = nxt; nxt = tmp;
        }

        // ---- epilogue L: relu; Q11 rowsums -> rsB; raw store ----
        float* rsm = (float*)smA;                   // [128][5]
        #pragma unroll
        for (int i = 0; i < 4; i++)
            #pragma unroll
            for (int j = 0; j < 4; j++)
                #pragma unroll
                for (int v = 0; v < 4; v++) acc[i][j][v] = fmaxf(acc[i][j][v], 0.0f);

        #pragma unroll
        for (int i = 0; i < 4; i++) {
            float s0 = 0.0f, s1 = 0.0f;
            #pragma unroll
            for (int j = 0; j < 4; j++) {
                s0 += acc[i][j][0] + acc[i][j][1];
                s1 += acc[i][j][2] + acc[i][j][3];
            }
            s0 += __shfl_xor_sync(0xffffffffu, s0, 1);
            s0 += __shfl_xor_sync(0xffffffffu, s0, 2);
            s1 += __shfl_xor_sync(0xffffffffu, s1, 1);
            s1 += __shfl_xor_sync(0xffffffffu, s1, 2);
            if (t4 == 0) {
                rsm[(wr + i * 16 + g) * 5 + (wid & 3)] = s0;
                rsm[(wr + i * 16 + g + 8) * 5 + (wid & 3)] = s1;
            }
        }
        #pragma unroll
        for (int i = 0; i < 4; i++) {
            int r0 = wr + i * 16 + g, r1 = r0 + 8;
            #pragma unroll
            for (int j = 0; j < 4; j++) {
                int c0 = wc + j * 8 + t4 * 2;
                *(unsigned*)&Sb[(long)(128 + r0) * NN + 128 + c0] = pk2(acc[i][j][0], acc[i][j][1]);
                *(unsigned*)&Sb[(long)(128 + r1) * NN + 128 + c0] = pk2(acc[i][j][2], acc[i][j][3]);
            }
        }
        __syncthreads();
        if (tid < 128)
            rsB[(long)bz * NN + 128 + tid] =
                rsm[tid*5] + rsm[tid*5+1] + rsm[tid*5+2] + rsm[tid*5+3];
    }
}

// ---------------- inv = wt / (rowsum + eps) -----------------------------------
__global__ __launch_bounds__(256) void inv_kernel(
    const float* __restrict__ rsA, const float* __restrict__ rsB, float* __restrict__ inv)
{
    int bz = blockIdx.x, n = threadIdx.x;
    int t = bz >> 5;
    float wt = 0.7f * powf(SKIPW, (float)(T_STEPS - 1 - t));
    float rs = rsA[(long)bz * NN + n];
    if (n >= 128) rs += rsB[(long)bz * NN + n];
    inv[(long)bz * NN + n] = wt / (rs + EPSV);
}

// ------- A = 0.3^16*sup + sum_t raw_t * inv_t[n] (fp16 in, fp32 out) -----------
__global__ __launch_bounds__(256) void reduce_kernel(
    const __half* __restrict__ S, const float* __restrict__ inv,
    const float* __restrict__ sup, float* __restrict__ A)
{
    long i4 = (long)blockIdx.x * 256 + threadIdx.x;
    const uint2* S2 = (const uint2*)S;
    const float4* P4 = (const float4*)sup;
    float4* A4 = (float4*)A;
    int b = (int)(i4 >> 14);
    long rem = i4 & 16383;
    int n = (int)(rem >> 6);
    const float k16 = 4.3046721e-8f;
    float4 p = P4[i4];
    float4 a = make_float4(p.x * k16, p.y * k16, p.z * k16, p.w * k16);
    #pragma unroll
    for (int t = 0; t < T_STEPS; t++) {
        int bz = t * BATCH + b;
        uint2 v = S2[(((long)bz) << 14) + rem];
        float iv = inv[(long)bz * NN + n];
        float2 v01 = __half22float2(*(__half2*)&v.x);
        float2 v23 = __half22float2(*(__half2*)&v.y);
        a.x += v01.x * iv; a.y += v01.y * iv;
        a.z += v23.x * iv; a.w += v23.y * iv;
    }
    A4[i4] = a;
}

// ------- prep: fold Wa/ba into gate weights; output fp16 (N,K) blocks ----------
__global__ void prep_kernel(
    const float* __restrict__ Wa, const float* __restrict__ Wr,
    const float* __restrict__ Wz, const float* __restrict__ Wh,
    const float* __restrict__ ba, const float* __restrict__ br,
    const float* __restrict__ bz, const float* __restrict__ bh,
    __half* __restrict__ Brz, __half* __restrict__ Bh_,
    float* __restrict__ brz2, float* __restrict__ bh2)
{
    int idx = blockIdx.x * blockDim.x + threadIdx.x;
    if (idx < 65536) {
        int n = idx >> 8, k = idx & 255, np = n & 127;
        const float* W = (n < 128) ? Wr : Wz;
        float v;
        if (k < 128) {
            v = 0.0f;
            for (int d = 0; d < 128; d++) v += Wa[k * 128 + d] * W[d * 128 + np];
        } else v = W[k * 128 + np];
        Brz[n * 256 + k] = __float2half(v);
    } else if (idx < 98304) {
        int e = idx - 65536, n = e >> 8, k = e & 255;
        float v;
        if (k < 128) {
            v = 0.0f;
            for (int d = 0; d < 128; d++) v += Wa[k * 128 + d] * Wh[d * 128 + n];
        } else v = Wh[k * 128 + n];
        Bh_[n * 256 + k] = __float2half(v);
    } else if (idx < 98560) {
        int n = idx - 98304, np = n & 127;
        const float* W = (n < 128) ? Wr : Wz;
        float v = (n < 128) ? br[np] : bz[np];
        for (int d = 0; d < 128; d++) v += ba[d] * W[d * 128 + np];
        brz2[n] = v;
    } else if (idx < 98688) {
        int n = idx - 98560;
        float v = bh[n];
        for (int d = 0; d < 128; d++) v += ba[d] * Wh[d * 128 + n];
        bh2[n] = v;
    }
}

// ---------------- per-batch (N,D) -> (D,N) transpose ---------------------------
__global__ void transpose_k(const float* __restrict__ src, float* __restrict__ dst)
{
    __shared__ float tile[32][33];
    int b = blockIdx.z;
    int n0 = blockIdx.x * 32, d0 = blockIdx.y * 32;
    const float* s = src + (long)b * NN * DD;
    float* o = dst + (long)b * NN * DD;
    #pragma unroll
    for (int k = 0; k < 4; k++)
        tile[threadIdx.y + k * 8][threadIdx.x] =
            s[(long)(n0 + threadIdx.y + k * 8) * DD + d0 + threadIdx.x];
    __syncthreads();
    #pragma unroll
    for (int k = 0; k < 4; k++)
        o[(long)(d0 + threadIdx.y + k * 8) * NN + n0 + threadIdx.x] =
            tile[threadIdx.x][threadIdx.y + k * 8];
}

// ---------------- fully fused GGNN step (32-row CTAs, 8 warps) -----------------
// grid (8, BATCH): each CTA owns 32 rows of one batch. Warp grid 2x4:
// wr=(wid>>2)*16, phases 1/3 cols (wid&3)*32, phase 2 cols (wid&3)*64.
__global__ __launch_bounds__(256) void ggnn_step(
    const float* __restrict__ A, const float* __restrict__ h_in,
    const float* __restrict__ hT_in,
    const __half* __restrict__ Brz, const float* __restrict__ brz,
    const __half* __restrict__ Bh, const float* __restrict__ bh,
    float* __restrict__ h_out, float* __restrict__ hT_out)
{
    extern __shared__ __align__(16) unsigned smG[];
    unsigned* sAm = smG;                  // [32][68]
    unsigned* sH  = sAm + 32 * 68;        // [32][68]
    unsigned* sRZ = sH  + 32 * 68;        // [32][132]
    unsigned* sB  = sRZ + 32 * 132;       // stream buffer (max [256][20])
    unsigned* sA1 = sB  + 256 * 20;       // [32][20]

    const int tid = threadIdx.x, lane = tid & 31, wid = tid >> 5;
    const int g = lane >> 2, t4 = lane & 3;
    const int b = blockIdx.y, r0 = blockIdx.x * 32;
    const int wr = (wid >> 2) * 16;       // {0,16}
    const int wcn = (wid & 3) * 32;       // {0,32,64,96}

    const float* Ab  = A + (long)b * NN * NN;
    const float* hb  = h_in + (long)b * NN * DD;
    const float* hTb = hT_in + (long)b * NN * DD;
    float* hob  = h_out + (long)b * NN * DD;
    float* hTob = hT_out + (long)b * NN * DD;

    #pragma unroll
    for (int i = 0; i < 4; i++) {
        int e = tid + i * 256;
        int r = e >> 5, c4 = e & 31;
        float4 v = *(const float4*)&hb[(long)(r0 + r) * DD + c4 * 4];
        *(uint2*)&sH[r * 68 + c4 * 2] = pk4(v);
    }

    // ================= Phase 1: am = A @ h (32x128, K=256) =================
    float acc1[4][4] = {};
    for (int kb = 0; kb < 256; kb += 32) {
        {
            int r = tid >> 3, c4i = tid & 7;
            float4 v = *(const float4*)&Ab[(long)(r0 + r) * NN + kb + c4i * 4];
            *(uint2*)&sA1[r * 20 + c4i * 2] = pk4(v);
        }
        #pragma unroll
        for (int i = 0; i < 4; i++) {
            int e = tid + i * 256;
            int d = e >> 3, nq = e & 7;
            float4 v = *(const float4*)&hTb[(long)d * NN + kb + nq * 4];
            *(uint2*)&sB[d * 18 + nq * 2] = pk4(v);
        }
        __syncthreads();
        #pragma unroll
        for (int k8 = 0; k8 < 2; k8++) {
            unsigned af[4], bf[4][2];
            int row = wr + g;
            af[0] = sA1[row * 20 + k8 * 8 + t4];
            af[1] = sA1[(row + 8) * 20 + k8 * 8 + t4];
            af[2] = sA1[row * 20 + k8 * 8 + t4 + 4];
            af[3] = sA1[(row + 8) * 20 + k8 * 8 + t4 + 4];
            #pragma unroll
            for (int j = 0; j < 4; j++) {
                int n = wcn + j * 8 + g;
                bf[j][0] = sB[n * 18 + k8 * 8 + t4];
                bf[j][1] = sB[n * 18 + k8 * 8 + t4 + 4];
            }
            #pragma unroll
            for (int j = 0; j < 4; j++)
                mma_f16(acc1[j], af, bf[j]);
        }
        __syncthreads();
    }
    {
        int row = wr + g;
        #pragma unroll
        for (int j = 0; j < 4; j++) {
            int colp = ((wcn + j * 8) >> 1) + t4;
            sAm[row * 68 + colp]       = pk2(acc1[j][0], acc1[j][1]);
            sAm[(row + 8) * 68 + colp] = pk2(acc1[j][2], acc1[j][3]);
        }
    }
    __syncthreads();

    // ================= Phase 2: [r|z] = sigmoid([am|h] @ Brz + brz2) ==========
    {
        const int wc2 = (wid & 3) * 64;
        float acc2[8][4] = {};
        for (int kb = 0; kb < 256; kb += 32) {
            #pragma unroll
            for (int i = 0; i < 4; i++) {
                int e = tid + i * 256;
                int n = e >> 2, c8 = e & 3;
                uint4 v = *(const uint4*)(Brz + (long)n * 256 + kb + c8 * 8);
                *(uint4*)&sB[n * 20 + c8 * 4] = v;
            }
            __syncthreads();
            const unsigned* src = (kb < 128) ? sAm : sH;
            #pragma unroll
            for (int k8 = 0; k8 < 2; k8++) {
                int pb = ((kb & 127) >> 1) + k8 * 8;
                unsigned af[4], bf[8][2];
                int row = wr + g;
                af[0] = src[row * 68 + pb + t4];
                af[1] = src[(row + 8) * 68 + pb + t4];
                af[2] = src[row * 68 + pb + t4 + 4];
                af[3] = src[(row + 8) * 68 + pb + t4 + 4];
                #pragma unroll
                for (int j = 0; j < 8; j++) {
                    int n = wc2 + j * 8 + g;
                    bf[j][0] = sB[n * 20 + k8 * 8 + t4];
                    bf[j][1] = sB[n * 20 + k8 * 8 + t4 + 4];
                }
                #pragma unroll
                for (int j = 0; j < 8; j++)
                    mma_f16(acc2[j], af, bf[j]);
            }
            __syncthreads();
        }
        {
            int row = wr + g;
            #pragma unroll
            for (int j = 0; j < 8; j++) {
                int col = wc2 + j * 8 + 2 * t4;
                float b0 = brz[col], b1 = brz[col + 1];
                float v00 = 1.0f / (1.0f + expf(-(acc2[j][0] + b0)));
                float v01 = 1.0f / (1.0f + expf(-(acc2[j][1] + b1)));
                float v10 = 1.0f / (1.0f + expf(-(acc2[j][2] + b0)));
                float v11 = 1.0f / (1.0f + expf(-(acc2[j][3] + b1)));
                sRZ[row * 132 + (col >> 1)]       = pk2(v00, v01);
                sRZ[(row + 8) * 132 + (col >> 1)] = pk2(v10, v11);
            }
        }
    }
    __syncthreads();

    // ================= Phase 3: GRU candidate + update ========================
    float acc3[4][4] = {};
    for (int kb = 0; kb < 256; kb += 32) {
        #pragma unroll
        for (int i = 0; i < 2; i++) {
            int e = tid + i * 256;
            int n = e >> 2, c8 = e & 3;
            uint4 v = *(const uint4*)(Bh + (long)n * 256 + kb + c8 * 8);
            *(uint4*)&sB[n * 20 + c8 * 4] = v;
        }
        __syncthreads();
        const bool lowK = (kb < 128);
        #pragma unroll
        for (int k8 = 0; k8 < 2; k8++) {
            int pb = ((kb & 127) >> 1) + k8 * 8;
            unsigned af[4], bf[4][2];
            int row = wr + g;
            if (lowK) {
                af[0] = sAm[row * 68 + pb + t4];
                af[1] = sAm[(row + 8) * 68 + pb + t4];
                af[2] = sAm[row * 68 + pb + t4 + 4];
                af[3] = sAm[(row + 8) * 68 + pb + t4 + 4];
            } else {
                af[0] = hmul2u(sRZ[row * 132 + pb + t4],       sH[row * 68 + pb + t4]);
                af[1] = hmul2u(sRZ[(row + 8) * 132 + pb + t4], sH[(row + 8) * 68 + pb + t4]);
                af[2] = hmul2u(sRZ[row * 132 + pb + t4 + 4],       sH[row * 68 + pb + t4 + 4]);
                af[3] = hmul2u(sRZ[(row + 8) * 132 + pb + t4 + 4], sH[(row + 8) * 68 + pb + t4 + 4]);
            }
            #pragma unroll
            for (int j = 0; j < 4; j++) {
                int n = wcn + j * 8 + g;
                bf[j][0] = sB[n * 20 + k8 * 8 + t4];
                bf[j][1] = sB[n * 20 + k8 * 8 + t4 + 4];
            }
            #pragma unroll
            for (int j = 0; j < 4; j++)
                mma_f16(acc3[j], af, bf[j]);
        }
        __syncthreads();
    }
    {
        int row = wr + g;
        int gr0 = r0 + row, gr1 = gr0 + 8;
        #pragma unroll
        for (int j = 0; j < 4; j++) {
            int col = wcn + j * 8 + 2 * t4;
            float bb0 = bh[col], bb1 = bh[col + 1];
            unsigned z0u = sRZ[row * 132 + 64 + (col >> 1)];
            unsigned z1u = sRZ[(row + 8) * 132 + 64 + (col >> 1)];
            float2 z0 = __half22float2(*(__half2*)&z0u);
            float2 z1 = __half22float2(*(__half2*)&z1u);
            float2 ho0 = *(const float2*)&hb[(long)gr0 * DD + col];
            float2 ho1 = *(const float2*)&hb[(long)gr1 * DD + col];
            float t00 = tanhf(acc3[j][0] + bb0);
            float t01 = tanhf(acc3[j][1] + bb1);
            float t10 = tanhf(acc3[j][2] + bb0);
            float t11 = tanhf(acc3[j][3] + bb1);
            float o00 = (1.0f - z0.x) * ho0.x + z0.x * t00;
            float o01 = (1.0f - z0.y) * ho0.y + z0.y * t01;
            float o10 = (1.0f - z1.x) * ho1.x + z1.x * t10;
            float o11 = (1.0f - z1.y) * ho1.y + z1.y * t11;
            *(float2*)&hob[(long)gr0 * DD + col] = make_float2(o00, o01);
            *(float2*)&hob[(long)gr1 * DD + col] = make_float2(o10, o11);
            hTob[(long)col * NN + gr0] = o00;
            hTob[(long)(col + 1) * NN + gr0] = o01;
            hTob[(long)col * NN + gr1] = o10;
            hTob[(long)(col + 1) * NN + gr1] = o11;
        }
    }
}

// ---------------- final classifier --------------------------------------------
__global__ __launch_bounds__(256) void fc_kernel(
    const float* __restrict__ h, const float* __restrict__ W,
    const float* __restrict__ bfc, float* __restrict__ out)
{
    int b = blockIdx.x, c = blockIdx.y;
    float s = 0.0f;
    for (int i = threadIdx.x; i < NN * DD; i += 256)
        s += h[(long)b * NN * DD + i] * W[(long)i * NCLS + c];
    #pragma unroll
    for (int o = 16; o; o >>= 1) s += __shfl_xor_sync(0xffffffffu, s, o);
    __shared__ float sh[8];
    if ((threadIdx.x & 31) == 0) sh[threadIdx.x >> 5] = s;
    __syncthreads();
    if (threadIdx.x == 0) {
        float t = 0.0f;
        for (int w = 0; w < 8; w++) t += sh[w];
        out[b * NCLS + c] = t + bfc[c];
    }
}

// ---------------- orchestration -----------------------------------------------
extern "C" void kernel_launch(void* const* d_in, const int* in_sizes, int n_in,
                              void* d_out, int out_size)
{
    const float* x        = (const float*)d_in[0];
    const float* supports = (const float*)d_in[1];
    const float* Wgl      = (const float*)d_in[2];
    const float* Wa       = (const float*)d_in[3];
    const float* ba       = (const float*)d_in[4];
    const float* Wr       = (const float*)d_in[5];
    const float* br       = (const float*)d_in[6];
    const float* Wz       = (const float*)d_in[7];
    const float* bz       = (const float*)d_in[8];
    const float* Wh       = (const float*)d_in[9];
    const float* bh       = (const float*)d_in[10];
    const float* Wfc      = (const float*)d_in[11];
    const float* bfc      = (const float*)d_in[12];
    float* out            = (float*)d_out;

    float *A0, *h0, *h1, *hT0, *hT1, *xT, *ri, *rsA, *rsB, *inv, *brz2, *bh2;
    __half *S, *Brz, *Bh_;
    cudaGetSymbolAddress((void**)&S,    g_S);
    cudaGetSymbolAddress((void**)&A0,   g_A0);
    cudaGetSymbolAddress((void**)&h0,   g_h0);
    cudaGetSymbolAddress((void**)&h1,   g_h1);
    cudaGetSymbolAddress((void**)&hT0,  g_hT0);
    cudaGetSymbolAddress((void**)&hT1,  g_hT1);
    cudaGetSymbolAddress((void**)&xT,   g_xT);
    cudaGetSymbolAddress((void**)&ri,   g_ri);
    cudaGetSymbolAddress((void**)&rsA,  g_rsA);
    cudaGetSymbolAddress((void**)&rsB,  g_rsB);
    cudaGetSymbolAddress((void**)&inv,  g_inv);
    cudaGetSymbolAddress((void**)&Brz,  g_Brz_h);
    cudaGetSymbolAddress((void**)&Bh_,  g_Bh_h);
    cudaGetSymbolAddress((void**)&brz2, g_brz2);
    cudaGetSymbolAddress((void**)&bh2,  g_bh2);

    const int GGNN_SMEM = (32*68 + 32*68 + 32*132 + 256*20 + 32*20) * 4;  // 57344
    static bool attr_set = false;
    if (!attr_set) {
        cudaFuncSetAttribute(att_kernel, cudaFuncAttributeMaxDynamicSharedMemorySize,
                             ATTA_BYTES);
        cudaFuncSetAttribute(ggnn_step, cudaFuncAttributeMaxDynamicSharedMemorySize,
                             GGNN_SMEM);
        attr_set = true;
    }

    prep_kernel<<<386, 256>>>(Wa, Wr, Wz, Wh, ba, br, bz, bh, Brz, Bh_, brz2, bh2);

    // ---- attention: merged symmetric 3-quadrant kernel ----
    rinv_kernel<<<T_STEPS * BATCH * NN, 128>>>(x, Wgl, ri);
    att_kernel<<<T_STEPS * BATCH, 256, ATTA_BYTES>>>(x, Wgl, ri, S, rsA, rsB);
    inv_kernel<<<T_STEPS * BATCH, 256>>>(rsA, rsB, inv);
    reduce_kernel<<<(BATCH * NN * NN / 4) / 256, 256>>>(S, inv, supports, A0);

    // ---- GGNN for last timestep only, 32-row CTAs ----
    const float* xt = x + (long)(T_STEPS - 1) * BATCH * NN * DD;
    transpose_k<<<dim3(8, 4, BATCH), dim3(32, 8)>>>(xt, xT);

    const float* hp  = xt;
    const float* hpT = xT;
    float* hn  = h0;
    float* hnT = hT0;
    for (int s = 0; s < GSTEPS; s++) {
        ggnn_step<<<dim3(8, BATCH), 256, GGNN_SMEM>>>(
            A0, hp, hpT, Brz, brz2, Bh_, bh2, hn, hnT);
        hp = hn; hpT = hnT;
        hn  = (hn == h0) ? h1 : h0;
        hnT = (hnT == hT0) ? hT1 : hT0;
    }

    fc_kernel<<<dim3(BATCH, NCLS), 256>>>(hp, Wfc, bfc, out);
    (void)in_sizes; (void)n_in; (void)out_size;
}

// round 17
// speedup vs baseline: 1.0562x; 1.0562x over previous
#include <cuda_runtime.h>
#include <cuda_fp16.h>
#include <math.h>
#include <stdint.h>

#define T_STEPS 16
#define BATCH   32
#define NN      256
#define DD      128
#define HEADS   16
#define KGL     (HEADS*DD)
#define GSTEPS  5
#define NCLS    2
#define SKIPW   0.3f
#define EPSV    1e-8f

// ---------------- scratch (device globals; no allocation allowed) ------------
__device__ __half g_S [(long)T_STEPS*BATCH*NN*NN];   // RAW relu(V V^T) fp16
__device__ float g_A0 [(long)BATCH*NN*NN];           // A_final
__device__ float g_h0 [(long)BATCH*NN*DD];
__device__ float g_h1 [(long)BATCH*NN*DD];
__device__ float g_hT0[(long)BATCH*NN*DD];
__device__ float g_hT1[(long)BATCH*NN*DD];
__device__ float g_xT [(long)BATCH*NN*DD];
__device__ float g_ri [(long)T_STEPS*BATCH*NN*HEADS];
__device__ float g_rsA[(long)T_STEPS*BATCH*NN];      // rowsums (n<128) + Q01 colsums (n>=128)
__device__ float g_rsB[(long)T_STEPS*BATCH*NN];      // Q11 rowsums (n>=128)
__device__ float g_inv[(long)T_STEPS*BATCH*NN];      // wt/(rowsum+eps)
__device__ __half g_Brz_h[2*DD*2*DD];
__device__ __half g_Bh_h [DD*2*DD];
__device__ float  g_brz2[2*DD];
__device__ float  g_bh2 [DD];

// ---------------- fp16 helpers -------------------------------------------------
__device__ __forceinline__ unsigned pk2(float a, float b) {
    __half2 h = __floats2half2_rn(a, b);
    return *(unsigned*)&h;
}
__device__ __forceinline__ uint2 pk4(float4 v) {
    return make_uint2(pk2(v.x, v.y), pk2(v.z, v.w));
}
__device__ __forceinline__ unsigned hmul2u(unsigned a, unsigned b) {
    __half2 r = __hmul2(*(__half2*)&a, *(__half2*)&b);
    return *(unsigned*)&r;
}
__device__ __forceinline__ void mma_f16(float c[4], const unsigned a[4], const unsigned b[2]) {
    asm volatile(
        "mma.sync.aligned.m16n8k16.row.col.f32.f16.f16.f32 "
        "{%0,%1,%2,%3}, {%4,%5,%6,%7}, {%8,%9}, {%0,%1,%2,%3};\n"
        : "+f"(c[0]), "+f"(c[1]), "+f"(c[2]), "+f"(c[3])
        : "r"(a[0]), "r"(a[1]), "r"(a[2]), "r"(a[3]), "r"(b[0]), "r"(b[1]));
}
__device__ __forceinline__ uint32_t smem_u32(const void* p) {
    uint32_t a;
    asm("{ .reg .u64 t; cvta.to.shared.u64 t, %1; cvt.u32.u64 %0, t; }" : "=r"(a) : "l"(p));
    return a;
}
__device__ __forceinline__ void ldsm_x4(unsigned& r0, unsigned& r1, unsigned& r2, unsigned& r3,
                                        uint32_t addr) {
    asm volatile("ldmatrix.sync.aligned.m8n8.x4.shared.b16 {%0,%1,%2,%3}, [%4];"
                 : "=r"(r0), "=r"(r1), "=r"(r2), "=r"(r3) : "r"(addr));
}

// ---------------- rinv: 0.25/(||x*w_h|| + eps) ---------------------------------
__global__ __launch_bounds__(128) void rinv_kernel(
    const float* __restrict__ x, const float* __restrict__ Wgl, float* __restrict__ rinv)
{
    long node = blockIdx.x;
    int tid = threadIdx.x, lane = tid & 31, w = tid >> 5;
    __shared__ float xs[DD];
    xs[tid] = x[node * DD + tid];
    __syncthreads();
    float4 xv = *(const float4*)&xs[lane * 4];
    #pragma unroll
    for (int hh = 0; hh < 4; hh++) {
        int h = w * 4 + hh;
        float4 wv = *(const float4*)&Wgl[h * DD + lane * 4];
        float a = xv.x * wv.x, b = xv.y * wv.y, c = xv.z * wv.z, d = xv.w * wv.w;
        float ss = a*a + b*b + c*c + d*d;
        #pragma unroll
        for (int o = 16; o; o >>= 1) ss += __shfl_xor_sync(0xffffffffu, ss, o);
        if (lane == 0) rinv[node * HEADS + h] = 0.25f / (sqrtf(ss) + EPSV);
    }
}

// ============ attention kernel A: rows 0-127 x cols 0-255 (Q00+Q01) ============
#define AT_ST0   0
#define AT_ST1   5120
#define AT_SX    10240      // 256 x 65 uints
#define AT_SR    26880      // 4096 floats
#define AT_SW    30976      // 2048 floats
#define AT_UINTS 33024
#define ATTA_BYTES (AT_UINTS * 4)

__global__ __launch_bounds__(256, 1) void att_a_kernel(
    const float* __restrict__ x, const float* __restrict__ Wgl,
    const float* __restrict__ rinv, __half* __restrict__ S,
    float* __restrict__ rsA)
{
    extern __shared__ __align__(16) unsigned smA[];
    unsigned* sX = smA + AT_SX;
    float* sR = (float*)(smA + AT_SR);
    float* sW = (float*)(smA + AT_SW);
    const uint32_t sb32 = smem_u32(smA);

    const int tid = threadIdx.x;
    const int lane = tid & 31, wid = tid >> 5;
    const int g = lane >> 2, t4 = lane & 3;
    const int wr = (wid >> 2) * 64;            // {0,64}
    const int wc = (wid & 3) * 64;             // {0,64,128,192}
    const int bz = blockIdx.x;

    const float* xb = x + (long)bz * NN * DD;
    const float* rb = rinv + (long)bz * NN * HEADS;
    __half* Sb = S + (long)bz * NN * NN;

    const int myN = tid >> 3;
    const int c4  = tid & 7;

    // ldmatrix per-lane base offsets (uint units, for i/p=0, k8=0)
    const int part = lane >> 3, lr = lane & 7;
    const int afu = (wr + (part & 1) * 8 + lr) * 20 + (part >> 1) * 4;
    const int bfu = (wc + (part >> 1) * 8 + lr) * 20 + (part & 1) * 4;

    #pragma unroll
    for (int it = 0; it < 32; it++) {
        int e = tid + it * 256, n = e >> 5, c = e & 31;
        float4 v = *(const float4*)&xb[(long)n * DD + c * 4];
        sX[n * 65 + c * 2]     = pk2(v.x, v.y);
        sX[n * 65 + c * 2 + 1] = pk2(v.z, v.w);
    }
    #pragma unroll
    for (int it = 0; it < 4; it++)
        ((float4*)sR)[tid + it * 256] = ((const float4*)rb)[tid + it * 256];
    #pragma unroll
    for (int it = 0; it < 2; it++)
        ((float4*)sW)[tid + it * 256] = ((const float4*)Wgl)[tid + it * 256];
    __syncthreads();

    float acc[4][8][4] = {};

    auto synth = [&](unsigned* buf, int kb) {
        int h = kb >> 7;
        int dof = (kb & 127) + c4 * 4;
        float4 ws = *(const float4*)&sW[kb + c4 * 4];
        #pragma unroll
        for (int it = 0; it < 8; it++) {
            int n = myN + it * 32;
            float rn = sR[n * 16 + h];
            int base = n * 65 + (dof >> 1);
            unsigned x0 = sX[base], x1 = sX[base + 1];
            float2 a = __half22float2(*(__half2*)&x0);
            float2 b = __half22float2(*(__half2*)&x1);
            buf[n * 20 + c4 * 2]     = pk2(a.x * ws.x * rn, a.y * ws.y * rn);
            buf[n * 20 + c4 * 2 + 1] = pk2(b.x * ws.z * rn, b.y * ws.w * rn);
        }
    };

    unsigned* B0 = smA + AT_ST0;
    unsigned* B1 = smA + AT_ST1;
    synth(B0, 0);
    __syncthreads();

    unsigned* cur = B0; unsigned* nxt = B1;
    int curOff = AT_ST0, nxtOff = AT_ST1;
    for (int kbi = 0; kbi < KGL / 32; kbi++) {
        uint32_t bufb = sb32 + (uint32_t)curOff * 4;
        #pragma unroll
        for (int k8 = 0; k8 < 2; k8++) {
            unsigned af[4][4], bf[8][2];
            #pragma unroll
            for (int i = 0; i < 4; i++)
                ldsm_x4(af[i][0], af[i][1], af[i][2], af[i][3],
                        bufb + (uint32_t)(afu + i * 320 + k8 * 8) * 4);
            #pragma unroll
            for (int p = 0; p < 4; p++)
                ldsm_x4(bf[2*p][0], bf[2*p][1], bf[2*p+1][0], bf[2*p+1][1],
                        bufb + (uint32_t)(bfu + p * 320 + k8 * 8) * 4);
            #pragma unroll
            for (int i = 0; i < 4; i++)
                #pragma unroll
                for (int j = 0; j < 8; j++)
                    mma_f16(acc[i][j], af[i], bf[j]);
        }
        if (kbi + 1 < KGL / 32) synth(nxt, (kbi + 1) * 32);
        __syncthreads();
        unsigned* tmp = cur; cur = nxt; nxt = tmp;
        int to = curOff; curOff = nxtOff; nxtOff = to;
    }

    // ---- epilogue: relu; raw store; rowsums; Q01 colsums; mirror Q01^T ----
    float* rsm = (float*)smA;                    // [128][5]
    float* csm = (float*)(smA + 640);            // [128][2]
    unsigned* Tm = smA + 1024;                   // [128][66] uints (transposed Q01)
    __half* Th = (__half*)Tm;                    // half stride 132

    #pragma unroll
    for (int i = 0; i < 4; i++)
        #pragma unroll
        for (int j = 0; j < 8; j++)
            #pragma unroll
            for (int v = 0; v < 4; v++) acc[i][j][v] = fmaxf(acc[i][j][v], 0.0f);

    #pragma unroll
    for (int i = 0; i < 4; i++) {
        float s0 = 0.0f, s1 = 0.0f;
        #pragma unroll
        for (int j = 0; j < 8; j++) {
            s0 += acc[i][j][0] + acc[i][j][1];
            s1 += acc[i][j][2] + acc[i][j][3];
        }
        s0 += __shfl_xor_sync(0xffffffffu, s0, 1);
        s0 += __shfl_xor_sync(0xffffffffu, s0, 2);
        s1 += __shfl_xor_sync(0xffffffffu, s1, 1);
        s1 += __shfl_xor_sync(0xffffffffu, s1, 2);
        if (t4 == 0) {
            rsm[(wr + i * 16 + g) * 5 + (wid & 3)] = s0;
            rsm[(wr + i * 16 + g + 8) * 5 + (wid & 3)] = s1;
        }
    }
    if ((wid & 3) >= 2) {
        #pragma unroll
        for (int j = 0; j < 8; j++) {
            float c0s = 0.0f, c1s = 0.0f;
            #pragma unroll
            for (int i = 0; i < 4; i++) {
                c0s += acc[i][j][0] + acc[i][j][2];
                c1s += acc[i][j][1] + acc[i][j][3];
            }
            c0s += __shfl_xor_sync(0xffffffffu, c0s, 4);
            c0s += __shfl_xor_sync(0xffffffffu, c0s, 8);
            c0s += __shfl_xor_sync(0xffffffffu, c0s, 16);
            c1s += __shfl_xor_sync(0xffffffffu, c1s, 4);
            c1s += __shfl_xor_sync(0xffffffffu, c1s, 8);
            c1s += __shfl_xor_sync(0xffffffffu, c1s, 16);
            if (g == 0) {
                int c = (wc - 128) + j * 8 + t4 * 2;
                csm[c * 2 + (wid >> 2)]       = c0s;
                csm[(c + 1) * 2 + (wid >> 2)] = c1s;
            }
        }
        #pragma unroll
        for (int i = 0; i < 4; i++) {
            int r0 = wr + i * 16 + g, r1 = r0 + 8;
            #pragma unroll
            for (int j = 0; j < 8; j++) {
                int c = (wc - 128) + j * 8 + t4 * 2;
                Th[c * 132 + r0]       = __float2half(acc[i][j][0]);
                Th[(c + 1) * 132 + r0] = __float2half(acc[i][j][1]);
                Th[c * 132 + r1]       = __float2half(acc[i][j][2]);
                Th[(c + 1) * 132 + r1] = __float2half(acc[i][j][3]);
            }
        }
    }
    #pragma unroll
    for (int i = 0; i < 4; i++) {
        int r0 = wr + i * 16 + g, r1 = r0 + 8;
        #pragma unroll
        for (int j = 0; j < 8; j++) {
            int c0 = wc + j * 8 + t4 * 2;
            *(unsigned*)&Sb[(long)r0 * NN + c0] = pk2(acc[i][j][0], acc[i][j][1]);
            *(unsigned*)&Sb[(long)r1 * NN + c0] = pk2(acc[i][j][2], acc[i][j][3]);
        }
    }
    __syncthreads();
    if (tid < 128) {
        rsA[(long)bz * NN + tid] =
            rsm[tid*5] + rsm[tid*5+1] + rsm[tid*5+2] + rsm[tid*5+3];
    } else {
        int c = tid - 128;
        rsA[(long)bz * NN + 128 + c] = csm[c*2] + csm[c*2+1];
    }
    #pragma unroll
    for (int it = 0; it < 32; it++) {
        int e = tid + it * 256;
        int rr = e >> 6, cc = e & 63;
        ((unsigned*)(Sb + (long)(128 + rr) * NN))[cc] = Tm[rr * 66 + cc];
    }
}

// ============ attention kernel B: Q11 only (rows x cols 128-255) ===============
#define BT_ST0   0
#define BT_ST1   2560
#define BT_SX    5120       // 128 x 65
#define BT_SR    13440      // 2048 floats
#define BT_SW    15488      // 2048 floats
#define BT_UINTS 17536
#define ATTB_BYTES (BT_UINTS * 4)

__global__ __launch_bounds__(256) void att_b_kernel(
    const float* __restrict__ x, const float* __restrict__ Wgl,
    const float* __restrict__ rinv, __half* __restrict__ S,
    float* __restrict__ rsB)
{
    extern __shared__ __align__(16) unsigned smB[];
    unsigned* sX = smB + BT_SX;
    float* sR = (float*)(smB + BT_SR);
    float* sW = (float*)(smB + BT_SW);
    const uint32_t sb32 = smem_u32(smB);

    const int tid = threadIdx.x;
    const int lane = tid & 31, wid = tid >> 5;
    const int g = lane >> 2, t4 = lane & 3;
    const int wr = (wid >> 2) * 64;            // {0,64}
    const int wc = (wid & 3) * 32;             // {0,32,64,96}
    const int bz = blockIdx.x;

    const float* xb = x + (long)bz * NN * DD;
    const float* rb = rinv + (long)bz * NN * HEADS;
    __half* Sb = S + (long)bz * NN * NN;

    const int myN = tid >> 3;                  // 0..31
    const int c4  = tid & 7;

    const int part = lane >> 3, lr = lane & 7;
    const int afu = (wr + (part & 1) * 8 + lr) * 20 + (part >> 1) * 4;
    const int bfu = (wc + (part >> 1) * 8 + lr) * 20 + (part & 1) * 4;

    #pragma unroll
    for (int it = 0; it < 16; it++) {
        int e = tid + it * 256, n = e >> 5, c = e & 31;
        float4 v = *(const float4*)&xb[(long)(128 + n) * DD + c * 4];
        sX[n * 65 + c * 2]     = pk2(v.x, v.y);
        sX[n * 65 + c * 2 + 1] = pk2(v.z, v.w);
    }
    #pragma unroll
    for (int it = 0; it < 2; it++)
        ((float4*)sR)[tid + it * 256] = ((const float4*)(rb + 128 * HEADS))[tid + it * 256];
    #pragma unroll
    for (int it = 0; it < 2; it++)
        ((float4*)sW)[tid + it * 256] = ((const float4*)Wgl)[tid + it * 256];
    __syncthreads();

    float acc[4][4][4] = {};

    auto synth = [&](unsigned* buf, int kb) {
        int h = kb >> 7;
        int dof = (kb & 127) + c4 * 4;
        float4 ws = *(const float4*)&sW[kb + c4 * 4];
        #pragma unroll
        for (int it = 0; it < 4; it++) {
            int n = myN + it * 32;             // 0..127 local
            float rn = sR[n * 16 + h];
            int base = n * 65 + (dof >> 1);
            unsigned x0 = sX[base], x1 = sX[base + 1];
            float2 a = __half22float2(*(__half2*)&x0);
            float2 b = __half22float2(*(__half2*)&x1);
            buf[n * 20 + c4 * 2]     = pk2(a.x * ws.x * rn, a.y * ws.y * rn);
            buf[n * 20 + c4 * 2 + 1] = pk2(b.x * ws.z * rn, b.y * ws.w * rn);
        }
    };

    unsigned* B0 = smB + BT_ST0;
    unsigned* B1 = smB + BT_ST1;
    synth(B0, 0);
    __syncthreads();

    unsigned* cur = B0; unsigned* nxt = B1;
    int curOff = BT_ST0, nxtOff = BT_ST1;
    for (int kbi = 0; kbi < KGL / 32; kbi++) {
        uint32_t bufb = sb32 + (uint32_t)curOff * 4;
        #pragma unroll
        for (int k8 = 0; k8 < 2; k8++) {
            unsigned af[4][4], bf[4][2];
            #pragma unroll
            for (int i = 0; i < 4; i++)
                ldsm_x4(af[i][0], af[i][1], af[i][2], af[i][3],
                        bufb + (uint32_t)(afu + i * 320 + k8 * 8) * 4);
            #pragma unroll
            for (int p = 0; p < 2; p++)
                ldsm_x4(bf[2*p][0], bf[2*p][1], bf[2*p+1][0], bf[2*p+1][1],
                        bufb + (uint32_t)(bfu + p * 320 + k8 * 8) * 4);
            #pragma unroll
            for (int i = 0; i < 4; i++)
                #pragma unroll
                for (int j = 0; j < 4; j++)
                    mma_f16(acc[i][j], af[i], bf[j]);
        }
        if (kbi + 1 < KGL / 32) synth(nxt, (kbi + 1) * 32);
        __syncthreads();
        unsigned* tmp = cur; cur = nxt; nxt = tmp;
        int to = curOff; curOff = nxtOff; nxtOff = to;
    }

    // ---- epilogue: relu; Q11 rowsums -> rsB; raw store ----
    float* rsm = (float*)smB;                   // [128][5]
    #pragma unroll
    for (int i = 0; i < 4; i++)
        #pragma unroll
        for (int j = 0; j < 4; j++)
            #pragma unroll
            for (int v = 0; v < 4; v++) acc[i][j][v] = fmaxf(acc[i][j][v], 0.0f);

    #pragma unroll
    for (int i = 0; i < 4; i++) {
        float s0 = 0.0f, s1 = 0.0f;
        #pragma unroll
        for (int j = 0; j < 4; j++) {
            s0 += acc[i][j][0] + acc[i][j][1];
            s1 += acc[i][j][2] + acc[i][j][3];
        }
        s0 += __shfl_xor_sync(0xffffffffu, s0, 1);
        s0 += __shfl_xor_sync(0xffffffffu, s0, 2);
        s1 += __shfl_xor_sync(0xffffffffu, s1, 1);
        s1 += __shfl_xor_sync(0xffffffffu, s1, 2);
        if (t4 == 0) {
            rsm[(wr + i * 16 + g) * 5 + (wid & 3)] = s0;
            rsm[(wr + i * 16 + g + 8) * 5 + (wid & 3)] = s1;
        }
    }
    #pragma unroll
    for (int i = 0; i < 4; i++) {
        int r0 = wr + i * 16 + g, r1 = r0 + 8;
        #pragma unroll
        for (int j = 0; j < 4; j++) {
            int c0 = wc + j * 8 + t4 * 2;
            *(unsigned*)&Sb[(long)(128 + r0) * NN + 128 + c0] = pk2(acc[i][j][0], acc[i][j][1]);
            *(unsigned*)&Sb[(long)(128 + r1) * NN + 128 + c0] = pk2(acc[i][j][2], acc[i][j][3]);
        }
    }
    __syncthreads();
    if (tid < 128)
        rsB[(long)bz * NN + 128 + tid] =
            rsm[tid*5] + rsm[tid*5+1] + rsm[tid*5+2] + rsm[tid*5+3];
}

// ---------------- inv = wt / (rowsum + eps) -----------------------------------
__global__ __launch_bounds__(256) void inv_kernel(
    const float* __restrict__ rsA, const float* __restrict__ rsB, float* __restrict__ inv)
{
    int bz = blockIdx.x, n = threadIdx.x;
    int t = bz >> 5;
    float wt = 0.7f * powf(SKIPW, (float)(T_STEPS - 1 - t));
    float rs = rsA[(long)bz * NN + n];
    if (n >= 128) rs += rsB[(long)bz * NN + n];
    inv[(long)bz * NN + n] = wt / (rs + EPSV);
}

// ------- A = 0.3^16*sup + sum_t raw_t * inv_t[n] (fp16 in, fp32 out) -----------
__global__ __launch_bounds__(256) void reduce_kernel(
    const __half* __restrict__ S, const float* __restrict__ inv,
    const float* __restrict__ sup, float* __restrict__ A)
{
    long i4 = (long)blockIdx.x * 256 + threadIdx.x;
    const uint2* S2 = (const uint2*)S;
    const float4* P4 = (const float4*)sup;
    float4* A4 = (float4*)A;
    int b = (int)(i4 >> 14);
    long rem = i4 & 16383;
    int n = (int)(rem >> 6);
    const float k16 = 4.3046721e-8f;
    float4 p = P4[i4];
    float4 a = make_float4(p.x * k16, p.y * k16, p.z * k16, p.w * k16);
    #pragma unroll
    for (int t = 0; t < T_STEPS; t++) {
        int bz = t * BATCH + b;
        uint2 v = S2[(((long)bz) << 14) + rem];
        float iv = inv[(long)bz * NN + n];
        float2 v01 = __half22float2(*(__half2*)&v.x);
        float2 v23 = __half22float2(*(__half2*)&v.y);
        a.x += v01.x * iv; a.y += v01.y * iv;
        a.z += v23.x * iv; a.w += v23.y * iv;
    }
    A4[i4] = a;
}

// ------- prep: fold Wa/ba into gate weights; output fp16 (N,K) blocks ----------
__global__ void prep_kernel(
    const float* __restrict__ Wa, const float* __restrict__ Wr,
    const float* __restrict__ Wz, const float* __restrict__ Wh,
    const float* __restrict__ ba, const float* __restrict__ br,
    const float* __restrict__ bz, const float* __restrict__ bh,
    __half* __restrict__ Brz, __half* __restrict__ Bh_,
    float* __restrict__ brz2, float* __restrict__ bh2)
{
    int idx = blockIdx.x * blockDim.x + threadIdx.x;
    if (idx < 65536) {
        int n = idx >> 8, k = idx & 255, np = n & 127;
        const float* W = (n < 128) ? Wr : Wz;
        float v;
        if (k < 128) {
            v = 0.0f;
            for (int d = 0; d < 128; d++) v += Wa[k * 128 + d] * W[d * 128 + np];
        } else v = W[k * 128 + np];
        Brz[n * 256 + k] = __float2half(v);
    } else if (idx < 98304) {
        int e = idx - 65536, n = e >> 8, k = e & 255;
        float v;
        if (k < 128) {
            v = 0.0f;
            for (int d = 0; d < 128; d++) v += Wa[k * 128 + d] * Wh[d * 128 + n];
        } else v = Wh[k * 128 + n];
        Bh_[n * 256 + k] = __float2half(v);
    } else if (idx < 98560) {
        int n = idx - 98304, np = n & 127;
        const float* W = (n < 128) ? Wr : Wz;
        float v = (n < 128) ? br[np] : bz[np];
        for (int d = 0; d < 128; d++) v += ba[d] * W[d * 128 + np];
        brz2[n] = v;
    } else if (idx < 98688) {
        int n = idx - 98560;
        float v = bh[n];
        for (int d = 0; d < 128; d++) v += ba[d] * Wh[d * 128 + n];
        bh2[n] = v;
    }
}

// ---------------- per-batch (N,D) -> (D,N) transpose ---------------------------
__global__ void transpose_k(const float* __restrict__ src, float* __restrict__ dst)
{
    __shared__ float tile[32][33];
    int b = blockIdx.z;
    int n0 = blockIdx.x * 32, d0 = blockIdx.y * 32;
    const float* s = src + (long)b * NN * DD;
    float* o = dst + (long)b * NN * DD;
    #pragma unroll
    for (int k = 0; k < 4; k++)
        tile[threadIdx.y + k * 8][threadIdx.x] =
            s[(long)(n0 + threadIdx.y + k * 8) * DD + d0 + threadIdx.x];
    __syncthreads();
    #pragma unroll
    for (int k = 0; k < 4; k++)
        o[(long)(d0 + threadIdx.y + k * 8) * NN + n0 + threadIdx.x] =
            tile[threadIdx.x][threadIdx.y + k * 8];
}

// ---------------- fully fused GGNN step (64-row CTAs, 8 warps) -----------------
__global__ __launch_bounds__(256) void ggnn_step(
    const float* __restrict__ A, const float* __restrict__ h_in,
    const float* __restrict__ hT_in,
    const __half* __restrict__ Brz, const float* __restrict__ brz,
    const __half* __restrict__ Bh, const float* __restrict__ bh,
    float* __restrict__ h_out, float* __restrict__ hT_out)
{
    extern __shared__ __align__(16) unsigned smG[];
    unsigned* sAm = smG;                  // [64][68]
    unsigned* sH  = sAm + 64 * 68;        // [64][68]
    unsigned* sRZ = sH  + 64 * 68;        // [64][132]
    unsigned* sB  = sRZ + 64 * 132;       // stream buffer (max [256][20])
    unsigned* sA1 = sB  + 256 * 20;       // [64][20]

    const int tid = threadIdx.x, lane = tid & 31, wid = tid >> 5;
    const int g = lane >> 2, t4 = lane & 3;
    const int b = blockIdx.y, r0 = blockIdx.x * 64;
    const int wr = (wid >> 1) * 16;
    const int wcn = (wid & 1) * 64;

    const float* Ab  = A + (long)b * NN * NN;
    const float* hb  = h_in + (long)b * NN * DD;
    const float* hTb = hT_in + (long)b * NN * DD;
    float* hob  = h_out + (long)b * NN * DD;
    float* hTob = hT_out + (long)b * NN * DD;

    #pragma unroll
    for (int i = 0; i < 8; i++) {
        int e = tid + i * 256;
        int r = e >> 5, c4 = e & 31;
        float4 v = *(const float4*)&hb[(long)(r0 + r) * DD + c4 * 4];
        *(uint2*)&sH[r * 68 + c4 * 2] = pk4(v);
    }

    // ================= Phase 1: am = A @ h =================
    float acc1[8][4] = {};
    for (int kb = 0; kb < 256; kb += 32) {
        #pragma unroll
        for (int i = 0; i < 2; i++) {
            int e = tid + i * 256;
            int r = e >> 3, c4 = e & 7;
            float4 v = *(const float4*)&Ab[(long)(r0 + r) * NN + kb + c4 * 4];
            *(uint2*)&sA1[r * 20 + c4 * 2] = pk4(v);
        }
        #pragma unroll
        for (int i = 0; i < 4; i++) {
            int e = tid + i * 256;
            int d = e >> 3, nq = e & 7;
            float4 v = *(const float4*)&hTb[(long)d * NN + kb + nq * 4];
            *(uint2*)&sB[d * 18 + nq * 2] = pk4(v);
        }
        __syncthreads();
        #pragma unroll
        for (int k8 = 0; k8 < 2; k8++) {
            unsigned af[4], bf[8][2];
            int row = wr + g;
            af[0] = sA1[row * 20 + k8 * 8 + t4];
            af[1] = sA1[(row + 8) * 20 + k8 * 8 + t4];
            af[2] = sA1[row * 20 + k8 * 8 + t4 + 4];
            af[3] = sA1[(row + 8) * 20 + k8 * 8 + t4 + 4];
            #pragma unroll
            for (int j = 0; j < 8; j++) {
                int n = wcn + j * 8 + g;
                bf[j][0] = sB[n * 18 + k8 * 8 + t4];
                bf[j][1] = sB[n * 18 + k8 * 8 + t4 + 4];
            }
            #pragma unroll
            for (int j = 0; j < 8; j++)
                mma_f16(acc1[j], af, bf[j]);
        }
        __syncthreads();
    }
    {
        int row = wr + g;
        #pragma unroll
        for (int j = 0; j < 8; j++) {
            int colp = ((wcn + j * 8) >> 1) + t4;
            sAm[row * 68 + colp]       = pk2(acc1[j][0], acc1[j][1]);
            sAm[(row + 8) * 68 + colp] = pk2(acc1[j][2], acc1[j][3]);
        }
    }
    __syncthreads();

    // ================= Phase 2: [r|z] = sigmoid([am|h] @ Brz + brz2) ==========
    {
        const int wc2 = (wid & 1) * 128;
        float acc2[16][4] = {};
        for (int kb = 0; kb < 256; kb += 32) {
            #pragma unroll
            for (int i = 0; i < 4; i++) {
                int e = tid + i * 256;
                int n = e >> 2, c8 = e & 3;
                uint4 v = *(const uint4*)(Brz + (long)n * 256 + kb + c8 * 8);
                *(uint4*)&sB[n * 20 + c8 * 4] = v;
            }
            __syncthreads();
            const unsigned* src = (kb < 128) ? sAm : sH;
            #pragma unroll
            for (int k8 = 0; k8 < 2; k8++) {
                int pb = ((kb & 127) >> 1) + k8 * 8;
                unsigned af[4], bf[16][2];
                int row = wr + g;
                af[0] = src[row * 68 + pb + t4];
                af[1] = src[(row + 8) * 68 + pb + t4];
                af[2] = src[row * 68 + pb + t4 + 4];
                af[3] = src[(row + 8) * 68 + pb + t4 + 4];
                #pragma unroll
                for (int j = 0; j < 16; j++) {
                    int n = wc2 + j * 8 + g;
                    bf[j][0] = sB[n * 20 + k8 * 8 + t4];
                    bf[j][1] = sB[n * 20 + k8 * 8 + t4 + 4];
                }
                #pragma unroll
                for (int j = 0; j < 16; j++)
                    mma_f16(acc2[j], af, bf[j]);
            }
            __syncthreads();
        }
        {
            int row = wr + g;
            #pragma unroll
            for (int j = 0; j < 16; j++) {
                int col = wc2 + j * 8 + 2 * t4;
                float b0 = brz[col], b1 = brz[col + 1];
                float v00 = 1.0f / (1.0f + expf(-(acc2[j][0] + b0)));
                float v01 = 1.0f / (1.0f + expf(-(acc2[j][1] + b1)));
                float v10 = 1.0f / (1.0f + expf(-(acc2[j][2] + b0)));
                float v11 = 1.0f / (1.0f + expf(-(acc2[j][3] + b1)));
                sRZ[row * 132 + (col >> 1)]       = pk2(v00, v01);
                sRZ[(row + 8) * 132 + (col >> 1)] = pk2(v10, v11);
            }
        }
    }
    __syncthreads();

    // ================= Phase 3: GRU candidate + update ========================
    float acc3[8][4] = {};
    for (int kb = 0; kb < 256; kb += 32) {
        #pragma unroll
        for (int i = 0; i < 2; i++) {
            int e = tid + i * 256;
            int n = e >> 2, c8 = e & 3;
            uint4 v = *(const uint4*)(Bh + (long)n * 256 + kb + c8 * 8);
            *(uint4*)&sB[n * 20 + c8 * 4] = v;
        }
        __syncthreads();
        const bool lowK = (kb < 128);
        #pragma unroll
        for (int k8 = 0; k8 < 2; k8++) {
            int pb = ((kb & 127) >> 1) + k8 * 8;
            unsigned af[4], bf[8][2];
            int row = wr + g;
            if (lowK) {
                af[0] = sAm[row * 68 + pb + t4];
                af[1] = sAm[(row + 8) * 68 + pb + t4];
                af[2] = sAm[row * 68 + pb + t4 + 4];
                af[3] = sAm[(row + 8) * 68 + pb + t4 + 4];
            } else {
                af[0] = hmul2u(sRZ[row * 132 + pb + t4],       sH[row * 68 + pb + t4]);
                af[1] = hmul2u(sRZ[(row + 8) * 132 + pb + t4], sH[(row + 8) * 68 + pb + t4]);
                af[2] = hmul2u(sRZ[row * 132 + pb + t4 + 4],       sH[row * 68 + pb + t4 + 4]);
                af[3] = hmul2u(sRZ[(row + 8) * 132 + pb + t4 + 4], sH[(row + 8) * 68 + pb + t4 + 4]);
            }
            #pragma unroll
            for (int j = 0; j < 8; j++) {
                int n = wcn + j * 8 + g;
                bf[j][0] = sB[n * 20 + k8 * 8 + t4];
                bf[j][1] = sB[n * 20 + k8 * 8 + t4 + 4];
            }
            #pragma unroll
            for (int j = 0; j < 8; j++)
                mma_f16(acc3[j], af, bf[j]);
        }
        __syncthreads();
    }
    {
        int row = wr + g;
        int gr0 = r0 + row, gr1 = gr0 + 8;
        #pragma unroll
        for (int j = 0; j < 8; j++) {
            int col = wcn + j * 8 + 2 * t4;
            float bb0 = bh[col], bb1 = bh[col + 1];
            unsigned z0u = sRZ[row * 132 + 64 + (col >> 1)];
            unsigned z1u = sRZ[(row + 8) * 132 + 64 + (col >> 1)];
            float2 z0 = __half22float2(*(__half2*)&z0u);
            float2 z1 = __half22float2(*(__half2*)&z1u);
            float2 ho0 = *(const float2*)&hb[(long)gr0 * DD + col];
            float2 ho1 = *(const float2*)&hb[(long)gr1 * DD + col];
            float t00 = tanhf(acc3[j][0] + bb0);
            float t01 = tanhf(acc3[j][1] + bb1);
            float t10 = tanhf(acc3[j][2] + bb0);
            float t11 = tanhf(acc3[j][3] + bb1);
            float o00 = (1.0f - z0.x) * ho0.x + z0.x * t00;
            float o01 = (1.0f - z0.y) * ho0.y + z0.y * t01;
            float o10 = (1.0f - z1.x) * ho1.x + z1.x * t10;
            float o11 = (1.0f - z1.y) * ho1.y + z1.y * t11;
            *(float2*)&hob[(long)gr0 * DD + col] = make_float2(o00, o01);
            *(float2*)&hob[(long)gr1 * DD + col] = make_float2(o10, o11);
            hTob[(long)col * NN + gr0] = o00;
            hTob[(long)(col + 1) * NN + gr0] = o01;
            hTob[(long)col * NN + gr1] = o10;
            hTob[(long)(col + 1) * NN + gr1] = o11;
        }
    }
}

// ---------------- final classifier --------------------------------------------
__global__ __launch_bounds__(256) void fc_kernel(
    const float* __restrict__ h, const float* __restrict__ W,
    const float* __restrict__ bfc, float* __restrict__ out)
{
    int b = blockIdx.x, c = blockIdx.y;
    float s = 0.0f;
    for (int i = threadIdx.x; i < NN * DD; i += 256)
        s += h[(long)b * NN * DD + i] * W[(long)i * NCLS + c];
    #pragma unroll
    for (int o = 16; o; o >>= 1) s += __shfl_xor_sync(0xffffffffu, s, o);
    __shared__ float sh[8];
    if ((threadIdx.x & 31) == 0) sh[threadIdx.x >> 5] = s;
    __syncthreads();
    if (threadIdx.x == 0) {
        float t = 0.0f;
        for (int w = 0; w < 8; w++) t += sh[w];
        out[b * NCLS + c] = t + bfc[c];
    }
}

// ---------------- orchestration -----------------------------------------------
extern "C" void kernel_launch(void* const* d_in, const int* in_sizes, int n_in,
                              void* d_out, int out_size)
{
    const float* x        = (const float*)d_in[0];
    const float* supports = (const float*)d_in[1];
    const float* Wgl      = (const float*)d_in[2];
    const float* Wa       = (const float*)d_in[3];
    const float* ba       = (const float*)d_in[4];
    const float* Wr       = (const float*)d_in[5];
    const float* br       = (const float*)d_in[6];
    const float* Wz       = (const float*)d_in[7];
    const float* bz       = (const float*)d_in[8];
    const float* Wh       = (const float*)d_in[9];
    const float* bh       = (const float*)d_in[10];
    const float* Wfc      = (const float*)d_in[11];
    const float* bfc      = (const float*)d_in[12];
    float* out            = (float*)d_out;

    float *A0, *h0, *h1, *hT0, *hT1, *xT, *ri, *rsA, *rsB, *inv, *brz2, *bh2;
    __half *S, *Brz, *Bh_;
    cudaGetSymbolAddress((void**)&S,    g_S);
    cudaGetSymbolAddress((void**)&A0,   g_A0);
    cudaGetSymbolAddress((void**)&h0,   g_h0);
    cudaGetSymbolAddress((void**)&h1,   g_h1);
    cudaGetSymbolAddress((void**)&hT0,  g_hT0);
    cudaGetSymbolAddress((void**)&hT1,  g_hT1);
    cudaGetSymbolAddress((void**)&xT,   g_xT);
    cudaGetSymbolAddress((void**)&ri,   g_ri);
    cudaGetSymbolAddress((void**)&rsA,  g_rsA);
    cudaGetSymbolAddress((void**)&rsB,  g_rsB);
    cudaGetSymbolAddress((void**)&inv,  g_inv);
    cudaGetSymbolAddress((void**)&Brz,  g_Brz_h);
    cudaGetSymbolAddress((void**)&Bh_,  g_Bh_h);
    cudaGetSymbolAddress((void**)&brz2, g_brz2);
    cudaGetSymbolAddress((void**)&bh2,  g_bh2);

    const int GGNN_SMEM = (64*68 + 64*68 + 64*132 + 256*20 + 64*20) * 4;  // 94208
    static bool attr_set = false;
    if (!attr_set) {
        cudaFuncSetAttribute(att_a_kernel, cudaFuncAttributeMaxDynamicSharedMemorySize,
                             ATTA_BYTES);
        cudaFuncSetAttribute(att_b_kernel, cudaFuncAttributeMaxDynamicSharedMemorySize,
                             ATTB_BYTES);
        cudaFuncSetAttribute(ggnn_step, cudaFuncAttributeMaxDynamicSharedMemorySize,
                             GGNN_SMEM);
        attr_set = true;
    }

    prep_kernel<<<386, 256>>>(Wa, Wr, Wz, Wh, ba, br, bz, bh, Brz, Bh_, brz2, bh2);

    // ---- attention: symmetric 3-quadrant scheme, raw fp16 + deferred norm ----
    rinv_kernel<<<T_STEPS * BATCH * NN, 128>>>(x, Wgl, ri);
    att_a_kernel<<<T_STEPS * BATCH, 256, ATTA_BYTES>>>(x, Wgl, ri, S, rsA);
    att_b_kernel<<<T_STEPS * BATCH, 256, ATTB_BYTES>>>(x, Wgl, ri, S, rsB);
    inv_kernel<<<T_STEPS * BATCH, 256>>>(rsA, rsB, inv);
    reduce_kernel<<<(BATCH * NN * NN / 4) / 256, 256>>>(S, inv, supports, A0);

    // ---- GGNN for last timestep only, one fused kernel per step ----
    const float* xt = x + (long)(T_STEPS - 1) * BATCH * NN * DD;
    transpose_k<<<dim3(8, 4, BATCH), dim3(32, 8)>>>(xt, xT);

    const float* hp  = xt;
    const float* hpT = xT;
    float* hn  = h0;
    float* hnT = hT0;
    for (int s = 0; s < GSTEPS; s++) {
        ggnn_step<<<dim3(4, BATCH), 256, GGNN_SMEM>>>(
            A0, hp, hpT, Brz, brz2, Bh_, bh2, hn, hnT);
        hp = hn; hpT = hnT;
        hn  = (hn == h0) ? h1 : h0;
        hnT = (hnT == hT0) ? hT1 : hT0;
    }

    fc_kernel<<<dim3(BATCH, NCLS), 256>>>(hp, Wfc, bfc, out);
    (void)in_sizes; (void)n_in; (void)out_size;
}